// round 4
// baseline (speedup 1.0000x reference)
#include <cuda_runtime.h>
#include <cstdint>

#define C_DIM  256
#define L_DIM  4096
#define LM_DIM 36864
#define B_DIM  4

__device__ float g_M[C_DIM * C_DIM];             // M[c1][c2]
__device__ float g_U[B_DIM * C_DIM * L_DIM];     // U[b][c2][l]

// ---------------- helpers ----------------
__device__ __forceinline__ uint32_t smem_u32(const void* p) {
    uint32_t a;
    asm("{ .reg .u64 t; cvta.to.shared.u64 t, %1; cvt.u32.u64 %0, t; }" : "=r"(a) : "l"(p));
    return a;
}
__device__ __forceinline__ void cp16(uint32_t dst, const void* src) {
    asm volatile("cp.async.cg.shared.global [%0], [%1], 16;" :: "r"(dst), "l"(src) : "memory");
}
__device__ __forceinline__ void cp_commit() {
    asm volatile("cp.async.commit_group;" ::: "memory");
}
template <int N>
__device__ __forceinline__ void cp_wait() {
    asm volatile("cp.async.wait_group %0;" :: "n"(N) : "memory");
}
__device__ __forceinline__ uint32_t tf32_hi(float v) {
    uint32_t h;
    asm("cvt.rna.tf32.f32 %0, %1;" : "=r"(h) : "f"(v));
    return h;
}
__device__ __forceinline__ uint32_t tf32_lo(float v, uint32_t hi) {
    float l = v - __uint_as_float(hi);
    uint32_t r;
    asm("cvt.rna.tf32.f32 %0, %1;" : "=r"(r) : "f"(l));
    return r;
}
__device__ __forceinline__ void mma8(float* d, const uint32_t* a, const uint32_t* b) {
    asm volatile(
        "mma.sync.aligned.m16n8k8.row.col.f32.tf32.tf32.f32 "
        "{%0,%1,%2,%3}, {%4,%5,%6,%7}, {%8,%9}, {%0,%1,%2,%3};"
        : "+f"(d[0]), "+f"(d[1]), "+f"(d[2]), "+f"(d[3])
        : "r"(a[0]), "r"(a[1]), "r"(a[2]), "r"(a[3]), "r"(b[0]), "r"(b[1]));
}
__device__ __forceinline__ unsigned long long fma2(unsigned long long a,
                                                   unsigned long long b,
                                                   unsigned long long c) {
    unsigned long long d;
    asm("fma.rn.f32x2 %0, %1, %2, %3;" : "=l"(d) : "l"(a), "l"(b), "l"(c));
    return d;
}
__device__ __forceinline__ unsigned long long dup2(float x) {
    unsigned long long d;
    unsigned int xi = __float_as_uint(x);
    asm("mov.b64 %0, {%1, %1};" : "=l"(d) : "r"(xi));
    return d;
}
__device__ __forceinline__ float lo32(unsigned long long v) {
    return __uint_as_float((unsigned int)(v & 0xffffffffull));
}
__device__ __forceinline__ float hi32(unsigned long long v) {
    return __uint_as_float((unsigned int)(v >> 32));
}

// profiler-alignment no-op
__global__ void dnop() {}

// ---------------- Kernel 1: M[c1][c2], k-split + atomicAdd ----------------
__global__ __launch_bounds__(256) void k1_M(const float* __restrict__ W1,
                                            const float* __restrict__ W2) {
    __shared__ float A[32][65];
    __shared__ float Bs[32][65];
    const int t = threadIdx.x;
    const int c2_0 = blockIdx.x * 32, c1_0 = blockIdx.y * 32, kk = blockIdx.z * 64;
    #pragma unroll
    for (int q = 0; q < 2; ++q) {
        int idx = t + q * 256;
        int r = idx >> 4, c4 = (idx & 15) * 4;
        float4 a = *(const float4*)&W1[(c1_0 + r) * 768 + kk + c4];
        A[r][c4] = a.x; A[r][c4 + 1] = a.y; A[r][c4 + 2] = a.z; A[r][c4 + 3] = a.w;
        float4 b = *(const float4*)&W2[(c2_0 + r) * 768 + 256 + kk + c4];
        Bs[r][c4] = b.x; Bs[r][c4 + 1] = b.y; Bs[r][c4 + 2] = b.z; Bs[r][c4 + 3] = b.w;
    }
    __syncthreads();
    const int ty = t >> 4, tx = t & 15;
    float a00 = 0.f, a01 = 0.f, a10 = 0.f, a11 = 0.f;
    #pragma unroll
    for (int k = 0; k < 64; ++k) {
        float x0 = A[ty * 2][k], x1 = A[ty * 2 + 1][k];
        float y0 = Bs[tx * 2][k], y1 = Bs[tx * 2 + 1][k];
        a00 += x0 * y0; a01 += x0 * y1; a10 += x1 * y0; a11 += x1 * y1;
    }
    atomicAdd(&g_M[(c1_0 + ty * 2)     * 256 + c2_0 + tx * 2],     a00);
    atomicAdd(&g_M[(c1_0 + ty * 2)     * 256 + c2_0 + tx * 2 + 1], a01);
    atomicAdd(&g_M[(c1_0 + ty * 2 + 1) * 256 + c2_0 + tx * 2],     a10);
    atomicAdd(&g_M[(c1_0 + ty * 2 + 1) * 256 + c2_0 + tx * 2 + 1], a11);
}

// ---------------- Kernel 2 (hybrid): tensor warps c2[0,128) + FFMA2 warps c2[128,256) ----------------
#define PA 136
#define CH_F (32 * PA)                       // 4352 floats / buffer
#define K2_SMEM (6 * CH_F * 4)               // 104448 B (A,Bt,Mf) x double buffer
#define UPITCH 132

__global__ __launch_bounds__(512, 1) void k2_U(const float* __restrict__ HSI) {
    extern __shared__ float sm[];
    const int t = threadIdx.x, wid = t >> 5, lane = t & 31;
    const int b = blockIdx.y, l0 = blockIdx.x * 128;
    const float* Hb = HSI + (size_t)b * C_DIM * L_DIM;
    const uint32_t sbase = smem_u32(sm);

    // ---- tensor-side ids (warps 0..7) ----
    const int g = lane >> 2, t4 = lane & 3;
    const int mw = (wid >> 1) * 32, nw = (wid & 1) * 64;
    float d[2][8][4];
    #pragma unroll
    for (int mt = 0; mt < 2; ++mt)
        #pragma unroll
        for (int nt = 0; nt < 8; ++nt)
            #pragma unroll
            for (int i = 0; i < 4; ++i) d[mt][nt][i] = 0.f;

    // ---- ffma-side ids (warps 8..15) ----
    const int fty = wid - 8;        // 0..7  -> c2_local = fty*16 + 2p
    const int ftx = lane;           // l = ftx*4 + j
    unsigned long long fa[8][4];
    #pragma unroll
    for (int p = 0; p < 8; ++p)
        #pragma unroll
        for (int j = 0; j < 4; ++j) fa[p][j] = 0ull;

    // ---- chunk 0 copies (all 512 threads) ----
    {
        float* A0 = sm; float* B0 = sm + CH_F; float* M0 = sm + 2 * CH_F;
        #pragma unroll
        for (int q2 = 0; q2 < 2; ++q2) {
            int q = t + q2 * 512;
            int r = q >> 5, qc = (q & 31) * 4;
            cp16(sbase + (uint32_t)((A0 - sm + r * PA + qc) * 4), &Hb[(size_t)r * L_DIM + l0 + qc]);
            cp16(sbase + (uint32_t)((B0 - sm + r * PA + qc) * 4), &g_M[r * 256 + qc]);
            cp16(sbase + (uint32_t)((M0 - sm + r * PA + qc) * 4), &g_M[r * 256 + 128 + qc]);
        }
        cp_commit();
    }

    for (int ch = 0; ch < 8; ++ch) {
        if (ch < 7) {
            int p = (ch + 1) & 1;
            int kk = (ch + 1) * 32;
            float* Ab = sm + p * 3 * CH_F;
            float* Bb = Ab + CH_F;
            float* Mb = Ab + 2 * CH_F;
            #pragma unroll
            for (int q2 = 0; q2 < 2; ++q2) {
                int q = t + q2 * 512;
                int r = q >> 5, qc = (q & 31) * 4;
                cp16(sbase + (uint32_t)((Ab - sm + r * PA + qc) * 4),
                     &Hb[(size_t)(kk + r) * L_DIM + l0 + qc]);
                cp16(sbase + (uint32_t)((Bb - sm + r * PA + qc) * 4), &g_M[(kk + r) * 256 + qc]);
                cp16(sbase + (uint32_t)((Mb - sm + r * PA + qc) * 4), &g_M[(kk + r) * 256 + 128 + qc]);
            }
            cp_commit();
            cp_wait<1>();
        } else {
            cp_wait<0>();
        }
        __syncthreads();

        const float* As = sm + (ch & 1) * 3 * CH_F;

        if (wid < 8) {
            // ================= tensor path: c2 [0,128) =================
            const float* Bs = As + CH_F;
            #pragma unroll
            for (int s = 0; s < 4; ++s) {
                const int r0 = 8 * s + t4, r1 = r0 + 4;
                uint32_t ah[2][4], al[2][4];
                #pragma unroll
                for (int mt = 0; mt < 2; ++mt) {
                    int m0 = mw + 16 * mt + g;
                    float v0 = As[r0 * PA + m0];
                    float v1 = As[r0 * PA + m0 + 8];
                    float v2 = As[r1 * PA + m0];
                    float v3 = As[r1 * PA + m0 + 8];
                    ah[mt][0] = tf32_hi(v0); al[mt][0] = tf32_lo(v0, ah[mt][0]);
                    ah[mt][1] = tf32_hi(v1); al[mt][1] = tf32_lo(v1, ah[mt][1]);
                    ah[mt][2] = tf32_hi(v2); al[mt][2] = tf32_lo(v2, ah[mt][2]);
                    ah[mt][3] = tf32_hi(v3); al[mt][3] = tf32_lo(v3, ah[mt][3]);
                }
                #pragma unroll
                for (int ng = 0; ng < 2; ++ng) {     // 2 groups of 4 n-tiles (reg cap)
                    uint32_t bh[4][2], bl[4][2];
                    #pragma unroll
                    for (int q = 0; q < 4; ++q) {
                        int nt = ng * 4 + q;
                        int n0 = nw + 8 * nt + g;
                        float v0 = Bs[r0 * PA + n0];
                        float v1 = Bs[r1 * PA + n0];
                        bh[q][0] = tf32_hi(v0); bl[q][0] = tf32_lo(v0, bh[q][0]);
                        bh[q][1] = tf32_hi(v1); bl[q][1] = tf32_lo(v1, bh[q][1]);
                    }
                    #pragma unroll
                    for (int mt = 0; mt < 2; ++mt)
                        #pragma unroll
                        for (int q = 0; q < 4; ++q)
                            mma8(d[mt][ng * 4 + q], ah[mt], bh[q]);
                    #pragma unroll
                    for (int mt = 0; mt < 2; ++mt)
                        #pragma unroll
                        for (int q = 0; q < 4; ++q)
                            mma8(d[mt][ng * 4 + q], ah[mt], bl[q]);
                    #pragma unroll
                    for (int mt = 0; mt < 2; ++mt)
                        #pragma unroll
                        for (int q = 0; q < 4; ++q)
                            mma8(d[mt][ng * 4 + q], al[mt], bh[q]);
                }
            }
        } else {
            // ================= FFMA2 path: c2 [128,256) =================
            const float* Mfs = As + 2 * CH_F;
            #pragma unroll 4
            for (int k = 0; k < 32; ++k) {
                float4 h = *(const float4*)&As[k * PA + ftx * 4];
                unsigned long long hd0 = dup2(h.x), hd1 = dup2(h.y);
                unsigned long long hd2 = dup2(h.z), hd3 = dup2(h.w);
                #pragma unroll
                for (int p = 0; p < 8; ++p) {
                    unsigned long long mp =
                        *(const unsigned long long*)&Mfs[k * PA + fty * 16 + 2 * p];
                    fa[p][0] = fma2(mp, hd0, fa[p][0]);
                    fa[p][1] = fma2(mp, hd1, fa[p][1]);
                    fa[p][2] = fma2(mp, hd2, fa[p][2]);
                    fa[p][3] = fma2(mp, hd3, fa[p][3]);
                }
            }
        }
        __syncthreads();
    }

    // ---------------- epilogue: stage through smem, coalesced stores ----------------
    float* Usm = sm;   // 128 x UPITCH floats
    float* Ub = g_U + (size_t)b * C_DIM * L_DIM;

    // pass 1: tensor half (c2 0..127)
    if (wid < 8) {
        #pragma unroll
        for (int mt = 0; mt < 2; ++mt) {
            int row0 = mw + 16 * mt + g;
            #pragma unroll
            for (int nt = 0; nt < 8; ++nt) {
                int col0 = nw + 8 * nt + 2 * t4;
                Usm[col0 * UPITCH + row0]           = d[mt][nt][0];
                Usm[(col0 + 1) * UPITCH + row0]     = d[mt][nt][1];
                Usm[col0 * UPITCH + row0 + 8]       = d[mt][nt][2];
                Usm[(col0 + 1) * UPITCH + row0 + 8] = d[mt][nt][3];
            }
        }
    }
    __syncthreads();
    for (int i = t; i < 128 * 32; i += 512) {
        int c2 = i >> 5, q = (i & 31) * 4;
        float4 v = *(const float4*)&Usm[c2 * UPITCH + q];
        *(float4*)&Ub[(size_t)c2 * L_DIM + l0 + q] = v;
    }
    __syncthreads();

    // pass 2: ffma half (c2 128..255)
    if (wid >= 8) {
        #pragma unroll
        for (int p = 0; p < 8; ++p) {
            int c2l = fty * 16 + 2 * p;
            float4 vlo = make_float4(lo32(fa[p][0]), lo32(fa[p][1]), lo32(fa[p][2]), lo32(fa[p][3]));
            float4 vhi = make_float4(hi32(fa[p][0]), hi32(fa[p][1]), hi32(fa[p][2]), hi32(fa[p][3]));
            *(float4*)&Usm[c2l * UPITCH + ftx * 4]       = vlo;
            *(float4*)&Usm[(c2l + 1) * UPITCH + ftx * 4] = vhi;
        }
    }
    __syncthreads();
    for (int i = t; i < 128 * 32; i += 512) {
        int c2 = i >> 5, q = (i & 31) * 4;
        float4 v = *(const float4*)&Usm[c2 * UPITCH + q];
        *(float4*)&Ub[(size_t)(128 + c2) * L_DIM + l0 + q] = v;
    }
}

// ---------------- Kernel 3: scores + argmax -> offsets ----------------
__global__ __launch_bounds__(288) void k3_attn(const float* __restrict__ MSI,
                                               float* __restrict__ out) {
    __shared__ __align__(16) float us[256][33];
    __shared__ float sc[288];
    const int t = threadIdx.x;
    const int b = blockIdx.y;
    const int l0 = blockIdx.x * 32;
    const int m0 = blockIdx.x * 288;
    const float* Mb = MSI + (size_t)b * C_DIM * LM_DIM;
    const float* Ub = g_U + (size_t)b * C_DIM * L_DIM;

    for (int i = t; i < 256 * 32; i += 288) {
        int c2 = i >> 5, l = i & 31;
        us[c2][l] = Ub[(size_t)c2 * L_DIM + l0 + l];
    }
    __syncthreads();

    const int m = m0 + t;
    const int ll = t / 9;
    const float* mp = Mb + m;
    float acc = 0.f;
    #pragma unroll 8
    for (int c2 = 0; c2 < 256; ++c2)
        acc += us[c2][ll] * mp[c2 * LM_DIM];
    sc[t] = acc;
    __syncthreads();

    if (t < 32) {
        float best = sc[t * 9];
        int bn = 0;
        #pragma unroll
        for (int j = 1; j < 9; ++j) {
            float v = sc[t * 9 + j];
            if (v > best) { best = v; bn = j; }
        }
        float2 o = make_float2((float)(bn / 3) - 1.f, (float)(bn % 3) - 1.f);
        *(float2*)&out[(size_t)(b * L_DIM + l0 + t) * 2] = o;
    }
}

// ---------------- launch ----------------
extern "C" void kernel_launch(void* const* d_in, const int* in_sizes, int n_in,
                              void* d_out, int out_size) {
    const float* HSI = (const float*)d_in[2];
    const float* MSI = (const float*)d_in[3];
    const float* W1  = (const float*)d_in[4];
    const float* W2  = (const float*)d_in[5];
    float* out = (float*)d_out;

    void* mp = nullptr;
    cudaGetSymbolAddress(&mp, g_M);
    cudaMemsetAsync(mp, 0, C_DIM * C_DIM * sizeof(float), 0);

    k1_M<<<dim3(8, 8, 4), 256>>>(W1, W2);

    // profiler alignment: shift ncu's skip so the captured launch is k2 (or k3)
    dnop<<<1, 32>>>();
    dnop<<<1, 32>>>();
    dnop<<<1, 32>>>();

    cudaFuncSetAttribute(k2_U, cudaFuncAttributeMaxDynamicSharedMemorySize, K2_SMEM);
    k2_U<<<dim3(32, 4), 512, K2_SMEM>>>(HSI);

    k3_attn<<<dim3(128, 4), 288>>>(MSI, out);
}